// round 9
// baseline (speedup 1.0000x reference)
#include <cuda_runtime.h>
#include <cstdint>

#define BS    128
#define HW    256
#define NPX   65536                // HW*HW
#define NTOT  (BS * NPX)           // 8,388,608
#define NEVEN (128 * 128)          // even-coord sites per batch

typedef unsigned long long ull;

// Scratch
__device__ ull      g_keys[NTOT];          // 67 MB: (epoch<<32)|p, winner = max
__device__ float4   g_pack[BS * NEVEN];    // 33.5 MB {m, conf, depth, 0} at even sites
__device__ int      g_nvalid[BS];
__device__ int      g_maskmax[BS];         // max p among masked px (for hot cell)
__device__ unsigned g_epoch;               // bumped once per launch

// ---------------------------------------------------------------------------
__global__ void k_init() {
    int t = threadIdx.x;
    if (t < BS) { g_nvalid[t] = 0; g_maskmax[t] = -1; }
    if (t == 0) g_epoch++;                 // stale keys become invalid
}

// ---------------------------------------------------------------------------
// k_fused: mask + count + packed even-site table + scatter, 4 px/thread.
//   valid px  -> atomicMax(keys[cell], ep|p)
//   masked px -> block-max p -> g_maskmax[b] (hot cell resolved in k_mid)
// ---------------------------------------------------------------------------
__global__ void __launch_bounds__(256)
k_fused(const float* __restrict__ grid, const float* __restrict__ seg,
        const float* __restrict__ conf, const float* __restrict__ depth) {
    int i4   = blockIdx.x * blockDim.x + threadIdx.x;   // float4 index
    int gidx = i4 << 2;
    int b    = gidx >> 16;
    int p0   = gidx & 0xFFFF;
    ull ep64 = ((ull)g_epoch) << 32;

    float4 s = reinterpret_cast<const float4*>(seg)[i4];
    bool m0 = s.x > 0.5f, m1 = s.y > 0.5f, m2 = s.z > 0.5f, m3 = s.w > 0.5f;
    bool mm[4] = {m0, m1, m2, m3};

    size_t gb4 = ((size_t)b * 2 * NPX + p0) >> 2;
    float4 gx = __ldcs(reinterpret_cast<const float4*>(grid) + gb4);
    float4 gy = __ldcs(reinterpret_cast<const float4*>(grid) + gb4 + NPX / 4);
    float xs[4] = {gx.x, gx.y, gx.z, gx.w};
    float ys[4] = {gy.x, gy.y, gy.z, gy.w};

    int localmax = -1;
    #pragma unroll
    for (int j = 0; j < 4; j++) {
        if (mm[j]) {
            // exact pow2 scaling: ((g+1)*0.5)*256, trunc toward zero, clip
            int ix = (int)(((xs[j] + 1.0f) * 0.5f) * 256.0f);
            int iy = (int)(((ys[j] + 1.0f) * 0.5f) * 256.0f);
            ix = min(max(ix, 0), HW - 1);
            iy = min(max(iy, 0), HW - 1);
            atomicMax(&g_keys[(b << 16) + (iy << 8) + ix], ep64 | (unsigned)(p0 + j));
        } else {
            localmax = p0 + j;
        }
    }

    // block reduce: valid count + masked max (block spans 1024 px, one batch)
    int cnt = (int)m0 + (int)m1 + (int)m2 + (int)m3;
    #pragma unroll
    for (int o = 16; o; o >>= 1) {
        cnt      += __shfl_down_sync(0xFFFFFFFFu, cnt, o);
        localmax  = max(localmax, __shfl_down_sync(0xFFFFFFFFu, localmax, o));
    }
    __shared__ int s_cnt[8], s_max[8];
    if ((threadIdx.x & 31) == 0) {
        s_cnt[threadIdx.x >> 5] = cnt;
        s_max[threadIdx.x >> 5] = localmax;
    }
    __syncthreads();
    if (threadIdx.x == 0) {
        int tc = 0, tm = -1;
        #pragma unroll
        for (int j = 0; j < 8; j++) { tc += s_cnt[j]; tm = max(tm, s_max[j]); }
        atomicAdd(&g_nvalid[b], tc);
        if (tm >= 0) atomicMax(&g_maskmax[b], tm);
    }

    // packed even-site table (warp = 128 contiguous px -> h uniform per warp)
    int h = p0 >> 8;
    if ((h & 1) == 0) {
        float4 c = __ldcs(reinterpret_cast<const float4*>(conf) + i4);
        float4 d = __ldcs(reinterpret_cast<const float4*>(depth) + i4);
        int w = p0 & 255;                               // even
        int site = b * NEVEN + (h >> 1) * 128 + (w >> 1);
        g_pack[site]     = make_float4(m0 ? 1.0f : 0.0f, c.x, d.x, 0.0f);
        g_pack[site + 1] = make_float4(m2 ? 1.0f : 0.0f, c.z, d.z, 0.0f);
    }
}

// ---------------------------------------------------------------------------
// k_mid: one block per batch. Normal: single hot-cell (128,128) atomic with
//        the masked-px winner. Fallback (nvalid==0): rescatter batch all-valid.
// ---------------------------------------------------------------------------
__global__ void __launch_bounds__(256)
k_mid(const float* __restrict__ grid) {
    int b  = blockIdx.x;
    int nv = g_nvalid[b];
    ull ep64 = ((ull)g_epoch) << 32;

    if (nv != 0) {
        if (threadIdx.x == 0) {
            int mx = g_maskmax[b];
            if (mx >= 0)
                atomicMax(&g_keys[(b << 16) + (128 << 8) + 128],
                          ep64 | (unsigned)mx);
        }
        return;
    }
    // fallback: all px valid, use real grid values (cold path)
    for (int i = threadIdx.x; i < NPX / 4; i += 256) {
        size_t gb4 = ((size_t)b * 2 * NPX) / 4 + i;
        float4 gx = reinterpret_cast<const float4*>(grid)[gb4];
        float4 gy = reinterpret_cast<const float4*>(grid)[gb4 + NPX / 4];
        float xs[4] = {gx.x, gx.y, gx.z, gx.w};
        float ys[4] = {gy.x, gy.y, gy.z, gy.w};
        int p0 = i << 2;
        #pragma unroll
        for (int j = 0; j < 4; j++) {
            int ix = (int)(((xs[j] + 1.0f) * 0.5f) * 256.0f);
            int iy = (int)(((ys[j] + 1.0f) * 0.5f) * 256.0f);
            ix = min(max(ix, 0), HW - 1);
            iy = min(max(iy, 0), HW - 1);
            atomicMax(&g_keys[(b << 16) + (iy << 8) + ix], ep64 | (unsigned)(p0 + j));
        }
    }
}

// ---------------------------------------------------------------------------
// k_gather: 4 px/thread. Stale-epoch key == empty == source (0,0).
//           key -> even site (h&~1, w&~1); one packed float4 load per px.
// ---------------------------------------------------------------------------
__global__ void __launch_bounds__(256)
k_gather(float* __restrict__ out) {
    int t    = blockIdx.x * blockDim.x + threadIdx.x;   // 4-px index
    int gidx = t << 2;
    int b    = gidx >> 16;
    unsigned ep = g_epoch;

    bool fb = (__ldg(&g_nvalid[b]) == 0);

    ulonglong2 ka = reinterpret_cast<const ulonglong2*>(g_keys)[t * 2];
    ulonglong2 kb = reinterpret_cast<const ulonglong2*>(g_keys)[t * 2 + 1];
    ull keys[4] = {ka.x, ka.y, kb.x, kb.y};

    float rx[4], ry[4], rd[4], rc[4], rm[4];
    #pragma unroll
    for (int j = 0; j < 4; j++) {
        ull k = keys[j];
        int p = ((unsigned)(k >> 32) == ep) ? (int)(unsigned)k : 0;
        int sx = p & 254;                 // even col
        int sy = (p >> 8) & 254;          // even row
        float4 pk = __ldg(&g_pack[b * NEVEN + (sy >> 1) * 128 + (sx >> 1)]);
        float m = fb ? 1.0f : pk.x;
        rd[j] = pk.z * m;
        rc[j] = pk.y;
        rx[j] = (float)sx * (1.0f / 280.0f) * m;
        ry[j] = (float)sy * (1.0f / 280.0f) * m;
        rm[j] = m;
    }

    float* dk = out;                                 // [BS,3,HW,HW]
    float* cf = out + (size_t)BS * 3 * NPX;          // [BS,1,HW,HW]
    float* mk = cf  + (size_t)BS * NPX;              // [BS,HW,HW]
    int p0 = gidx & 0xFFFF;
    size_t db4 = ((size_t)b * 3 * NPX + p0) >> 2;
    __stcs(reinterpret_cast<float4*>(dk) + db4,
           make_float4(rx[0], rx[1], rx[2], rx[3]));
    __stcs(reinterpret_cast<float4*>(dk) + db4 + NPX / 4,
           make_float4(ry[0], ry[1], ry[2], ry[3]));
    __stcs(reinterpret_cast<float4*>(dk) + db4 + NPX / 2,
           make_float4(rd[0], rd[1], rd[2], rd[3]));
    __stcs(reinterpret_cast<float4*>(cf) + t,
           make_float4(rc[0], rc[1], rc[2], rc[3]));
    __stcs(reinterpret_cast<float4*>(mk) + t,
           make_float4(rm[0], rm[1], rm[2], rm[3]));
}

// ---------------------------------------------------------------------------
extern "C" void kernel_launch(void* const* d_in, const int* in_sizes, int n_in,
                              void* d_out, int out_size) {
    const float* grid    = (const float*)d_in[0];
    const float* seg     = (const float*)d_in[1];
    const float* conf_is = (const float*)d_in[2];
    const float* depth   = (const float*)d_in[3];
    float* out = (float*)d_out;
    (void)in_sizes; (void)n_in; (void)out_size;

    k_init<<<1, 128>>>();
    k_fused<<<NTOT / 4 / 256, 256>>>(grid, seg, conf_is, depth);
    k_mid<<<BS, 256>>>(grid);
    k_gather<<<NTOT / 4 / 256, 256>>>(out);
}

// round 10
// speedup vs baseline: 1.2321x; 1.2321x over previous
#include <cuda_runtime.h>
#include <cstdint>

#define BS    128
#define HW    256
#define NPX   65536                // HW*HW
#define NTOT  (BS * NPX)           // 8,388,608
#define NEVEN (128 * 128)          // even-coord sites per batch

// Scratch
__device__ int    g_keys[NTOT];          // 33.5 MB: winner = max p (h*256+w)
__device__ float4 g_pack[BS * NEVEN];    // 33.5 MB {m, conf, depth, 0} at even sites
__device__ int    g_nvalid[BS];

// ---------------------------------------------------------------------------
// k_fused: mask + count + packed even-site table + scatter, 4 px/thread.
//   valid px  -> atomicMax(keys[cell], p)   (spread, no-return -> REDG)
//   masked px -> block-max p -> ONE hot-cell (128,128) atomic per block
// ---------------------------------------------------------------------------
__global__ void __launch_bounds__(256)
k_fused(const float* __restrict__ grid, const float* __restrict__ seg,
        const float* __restrict__ conf, const float* __restrict__ depth) {
    int i4   = blockIdx.x * blockDim.x + threadIdx.x;   // float4 index
    int gidx = i4 << 2;
    int b    = gidx >> 16;
    int p0   = gidx & 0xFFFF;

    float4 s = reinterpret_cast<const float4*>(seg)[i4];
    bool mm[4] = {s.x > 0.5f, s.y > 0.5f, s.z > 0.5f, s.w > 0.5f};

    size_t gb4 = ((size_t)b * 2 * NPX + p0) >> 2;
    float4 gx = __ldcs(reinterpret_cast<const float4*>(grid) + gb4);
    float4 gy = __ldcs(reinterpret_cast<const float4*>(grid) + gb4 + NPX / 4);
    float xs[4] = {gx.x, gx.y, gx.z, gx.w};
    float ys[4] = {gy.x, gy.y, gy.z, gy.w};

    int localmax = -1;
    #pragma unroll
    for (int j = 0; j < 4; j++) {
        if (mm[j]) {
            // exact pow2 scaling: ((g+1)*0.5)*256, trunc toward zero, clip
            int ix = (int)(((xs[j] + 1.0f) * 0.5f) * 256.0f);
            int iy = (int)(((ys[j] + 1.0f) * 0.5f) * 256.0f);
            ix = min(max(ix, 0), HW - 1);
            iy = min(max(iy, 0), HW - 1);
            atomicMax(&g_keys[(b << 16) + (iy << 8) + ix], p0 + j);
        } else {
            localmax = p0 + j;                  // masked px target (128,128)
        }
    }

    // block reduce: valid count + masked-px max (block = 1024 px, one batch)
    int cnt = (int)mm[0] + (int)mm[1] + (int)mm[2] + (int)mm[3];
    int wm  = __reduce_max_sync(0xFFFFFFFFu, localmax);
    #pragma unroll
    for (int o = 16; o; o >>= 1) cnt += __shfl_down_sync(0xFFFFFFFFu, cnt, o);
    __shared__ int s_cnt[8], s_max[8];
    if ((threadIdx.x & 31) == 0) {
        s_cnt[threadIdx.x >> 5] = cnt;
        s_max[threadIdx.x >> 5] = wm;
    }
    __syncthreads();
    if (threadIdx.x == 0) {
        int tc = 0, tm = -1;
        #pragma unroll
        for (int j = 0; j < 8; j++) { tc += s_cnt[j]; tm = max(tm, s_max[j]); }
        atomicAdd(&g_nvalid[b], tc);
        if (tm >= 0)
            atomicMax(&g_keys[(b << 16) + (128 << 8) + 128], tm);
    }

    // packed even-site table (warp = 128 contiguous px -> h uniform per warp)
    int h = p0 >> 8;
    if ((h & 1) == 0) {
        float4 c = __ldcs(reinterpret_cast<const float4*>(conf) + i4);
        float4 d = __ldcs(reinterpret_cast<const float4*>(depth) + i4);
        int w = p0 & 255;                               // even
        int site = b * NEVEN + (h >> 1) * 128 + (w >> 1);
        g_pack[site]     = make_float4(mm[0] ? 1.0f : 0.0f, c.x, d.x, 0.0f);
        g_pack[site + 1] = make_float4(mm[2] ? 1.0f : 0.0f, c.z, d.z, 0.0f);
    }
}

// ---------------------------------------------------------------------------
// k_fix: one block per batch. Cold fallback: if nvalid==0, the hot-cell write
//        above was wrong and no spread scatters happened -> reset hot cell,
//        rescatter the whole batch as all-valid.
// ---------------------------------------------------------------------------
__global__ void __launch_bounds__(256)
k_fix(const float* __restrict__ grid) {
    int b = blockIdx.x;
    if (g_nvalid[b] != 0) return;

    if (threadIdx.x == 0)
        g_keys[(b << 16) + (128 << 8) + 128] = 0;       // undo masked-max write
    __threadfence();
    __syncthreads();

    for (int i = threadIdx.x; i < NPX / 4; i += 256) {
        size_t gb4 = ((size_t)b * 2 * NPX) / 4 + i;
        float4 gx = reinterpret_cast<const float4*>(grid)[gb4];
        float4 gy = reinterpret_cast<const float4*>(grid)[gb4 + NPX / 4];
        float xs[4] = {gx.x, gx.y, gx.z, gx.w};
        float ys[4] = {gy.x, gy.y, gy.z, gy.w};
        int p0 = i << 2;
        #pragma unroll
        for (int j = 0; j < 4; j++) {
            int ix = (int)(((xs[j] + 1.0f) * 0.5f) * 256.0f);
            int iy = (int)(((ys[j] + 1.0f) * 0.5f) * 256.0f);
            ix = min(max(ix, 0), HW - 1);
            iy = min(max(iy, 0), HW - 1);
            atomicMax(&g_keys[(b << 16) + (iy << 8) + ix], p0 + j);
        }
    }
}

// ---------------------------------------------------------------------------
// k_gather: 4 px/thread. key -> even site (h&~1, w&~1); one packed float4
//           load per px (empty cell == key 0 == source (0,0)).
// ---------------------------------------------------------------------------
__global__ void __launch_bounds__(256)
k_gather(float* __restrict__ out) {
    int t    = blockIdx.x * blockDim.x + threadIdx.x;   // int4 index
    int gidx = t << 2;
    int b    = gidx >> 16;

    bool fb = (__ldg(&g_nvalid[b]) == 0);
    int4 key = reinterpret_cast<const int4*>(g_keys)[t];

    int keys[4] = {key.x, key.y, key.z, key.w};
    float rx[4], ry[4], rd[4], rc[4], rm[4];
    #pragma unroll
    for (int j = 0; j < 4; j++) {
        int k  = keys[j];
        int sx = k & 254;                 // even col
        int sy = (k >> 8) & 254;          // even row
        float4 pk = __ldg(&g_pack[b * NEVEN + (sy >> 1) * 128 + (sx >> 1)]);
        float m = fb ? 1.0f : pk.x;
        rd[j] = pk.z * m;
        rc[j] = pk.y;
        rx[j] = (float)sx * (1.0f / 280.0f) * m;
        ry[j] = (float)sy * (1.0f / 280.0f) * m;
        rm[j] = m;
    }

    float* dk = out;                                 // [BS,3,HW,HW]
    float* cf = out + (size_t)BS * 3 * NPX;          // [BS,1,HW,HW]
    float* mk = cf  + (size_t)BS * NPX;              // [BS,HW,HW]
    int p0 = gidx & 0xFFFF;
    size_t db4 = ((size_t)b * 3 * NPX + p0) >> 2;
    __stcs(reinterpret_cast<float4*>(dk) + db4,
           make_float4(rx[0], rx[1], rx[2], rx[3]));
    __stcs(reinterpret_cast<float4*>(dk) + db4 + NPX / 4,
           make_float4(ry[0], ry[1], ry[2], ry[3]));
    __stcs(reinterpret_cast<float4*>(dk) + db4 + NPX / 2,
           make_float4(rd[0], rd[1], rd[2], rd[3]));
    __stcs(reinterpret_cast<float4*>(cf) + t,
           make_float4(rc[0], rc[1], rc[2], rc[3]));
    __stcs(reinterpret_cast<float4*>(mk) + t,
           make_float4(rm[0], rm[1], rm[2], rm[3]));
}

// ---------------------------------------------------------------------------
extern "C" void kernel_launch(void* const* d_in, const int* in_sizes, int n_in,
                              void* d_out, int out_size) {
    const float* grid    = (const float*)d_in[0];
    const float* seg     = (const float*)d_in[1];
    const float* conf_is = (const float*)d_in[2];
    const float* depth   = (const float*)d_in[3];
    float* out = (float*)d_out;
    (void)in_sizes; (void)n_in; (void)out_size;

    void* keys_ptr = nullptr;
    void* nv_ptr   = nullptr;
    cudaGetSymbolAddress(&keys_ptr, g_keys);
    cudaGetSymbolAddress(&nv_ptr,   g_nvalid);
    cudaMemsetAsync(keys_ptr, 0, sizeof(int) * NTOT);
    cudaMemsetAsync(nv_ptr,   0, sizeof(int) * BS);

    k_fused<<<NTOT / 4 / 256, 256>>>(grid, seg, conf_is, depth);
    k_fix<<<BS, 256>>>(grid);
    k_gather<<<NTOT / 4 / 256, 256>>>(out);
}